// round 1
// baseline (speedup 1.0000x reference)
#include <cuda_runtime.h>

#define A_TOT   68
#define ROWS    128
#define TPB     128
#define STRIDE  69        // 69 is odd -> conflict-free per-thread row reads
#define MAXB    16384

__device__ float g_x[A_TOT];          // segmented log_softmax of current_action
__device__ float g_partials[MAXB];    // per-block partial sums

// ---------------------------------------------------------------------------
// Init: compute x = segmented log_softmax(current_action). Trivial serial work.
// ---------------------------------------------------------------------------
__global__ void init_kernel(const float* __restrict__ cur) {
    if (threadIdx.x == 0 && blockIdx.x == 0) {
        const int offs[7] = {0, 3, 6, 10, 35, 60, 68};
        for (int s = 0; s < 6; s++) {
            int b = offs[s], e = offs[s + 1];
            float m = -1e30f;
            for (int i = b; i < e; i++) m = fmaxf(m, cur[i]);
            float sum = 0.f;
            for (int i = b; i < e; i++) sum += expf(cur[i] - m);
            float ls = logf(sum);
            for (int i = b; i < e; i++) g_x[i] = cur[i] - m - ls;
        }
    }
}

// ---------------------------------------------------------------------------
// Per-segment loss with ONE exp per element, one log + one div per segment:
//   sum_i p_i (t_i - x_i) = (sum e_i*d_i - sum e_i*x_i)/s - log(s)
//   d_i = z_i - m, e_i = exp(d_i), s = sum e_i
// ---------------------------------------------------------------------------
template <int N>
__device__ __forceinline__ float seg_loss(const float* __restrict__ row,
                                          const float* __restrict__ sx,
                                          float inv_n) {
    float z[N];
    float m = -1e30f;
#pragma unroll
    for (int i = 0; i < N; i++) { z[i] = row[i]; m = fmaxf(m, z[i]); }
    float s = 0.f, w = 0.f, xs = 0.f;
#pragma unroll
    for (int i = 0; i < N; i++) {
        float d = z[i] - m;
        float e = __expf(d);
        s += e;
        w  = fmaf(e, d, w);
        xs = fmaf(e, sx[i], xs);
    }
    float inv_s = 1.0f / s;
    float ls = __logf(s);
    return inv_n * ((w - xs) * inv_s - ls);
}

// ---------------------------------------------------------------------------
// Main: one block = 128 rows staged in smem; one thread = one row.
// ---------------------------------------------------------------------------
__global__ void __launch_bounds__(TPB)
main_kernel(const float* __restrict__ prev, int W) {
    __shared__ float tile[ROWS * STRIDE];
    __shared__ float sx[A_TOT];
    __shared__ float red[TPB / 32];

    const int t  = threadIdx.x;
    const int r0 = blockIdx.x * ROWS;
    const int rows_here = min(ROWS, W - r0);

    if (t < A_TOT) sx[t] = g_x[t];

    // Coalesced float4 staging: 68 floats/row = 17 float4 (row-aligned).
    const float4* base =
        reinterpret_cast<const float4*>(prev + (size_t)r0 * A_TOT);
    const int n4 = rows_here * 17;
#pragma unroll
    for (int k = 0; k < 17; k++) {
        int idx4 = t + k * TPB;
        if (idx4 < n4) {
            float4 v = base[idx4];
            int r  = idx4 / 17;
            int c4 = idx4 - r * 17;
            float* dst = &tile[r * STRIDE + c4 * 4];
            dst[0] = v.x; dst[1] = v.y; dst[2] = v.z; dst[3] = v.w;
        }
    }
    __syncthreads();

    float acc = 0.f;
    if (t < rows_here) {
        const float* row = &tile[t * STRIDE];
        acc += seg_loss<3> (row + 0,  sx + 0,  1.f / 3.f);
        acc += seg_loss<3> (row + 3,  sx + 3,  1.f / 3.f);
        acc += seg_loss<4> (row + 6,  sx + 6,  0.25f);
        acc += seg_loss<25>(row + 10, sx + 10, 0.04f);
        acc += seg_loss<25>(row + 35, sx + 35, 0.04f);
        acc += seg_loss<8> (row + 60, sx + 60, 0.125f);
    }

    // Deterministic block reduction.
#pragma unroll
    for (int o = 16; o > 0; o >>= 1)
        acc += __shfl_xor_sync(0xffffffffu, acc, o);
    if ((t & 31) == 0) red[t >> 5] = acc;
    __syncthreads();
    if (t == 0)
        g_partials[blockIdx.x] = red[0] + red[1] + red[2] + red[3];
}

// ---------------------------------------------------------------------------
// Final deterministic tree reduce of block partials.
// ---------------------------------------------------------------------------
__global__ void reduce_kernel(float* __restrict__ out, int nblocks, float inv_W) {
    __shared__ float sm[32];
    float a = 0.f;
    for (int i = threadIdx.x; i < nblocks; i += blockDim.x)
        a += g_partials[i];
#pragma unroll
    for (int o = 16; o > 0; o >>= 1)
        a += __shfl_xor_sync(0xffffffffu, a, o);
    if ((threadIdx.x & 31) == 0) sm[threadIdx.x >> 5] = a;
    __syncthreads();
    if (threadIdx.x < 32) {
        float b = (threadIdx.x < blockDim.x / 32) ? sm[threadIdx.x] : 0.f;
#pragma unroll
        for (int o = 16; o > 0; o >>= 1)
            b += __shfl_xor_sync(0xffffffffu, b, o);
        if (threadIdx.x == 0) out[0] = b * inv_W;
    }
}

// ---------------------------------------------------------------------------
extern "C" void kernel_launch(void* const* d_in, const int* in_sizes, int n_in,
                              void* d_out, int out_size) {
    const float* cur  = (const float*)d_in[0];
    const float* prev = (const float*)d_in[1];
    float* out = (float*)d_out;

    int W = in_sizes[1] / A_TOT;
    int nblocks = (W + ROWS - 1) / ROWS;
    if (nblocks > MAXB) nblocks = MAXB;  // safety; W=524288 -> 4096 blocks

    init_kernel<<<1, 1>>>(cur);
    main_kernel<<<nblocks, TPB>>>(prev, W);
    reduce_kernel<<<1, 1024>>>(out, nblocks, 1.0f / (float)W);
}